// round 1
// baseline (speedup 1.0000x reference)
#include <cuda_runtime.h>

#define N_NODES 100000
#define N_EDGES 1600000
#define N_GRAPHS 512
#define K0DIM 102
#define K0P 104     // padded feature dim (pad cols 102,103 are zero)
#define HID 128
#define NCAT 10

// ---------------- scratch (device globals; no runtime allocation) ----------------
__device__ __align__(16) float g_x0[N_NODES * K0P];     // layer-0 input features
__device__ __align__(16) float g_agg0[N_NODES * K0P];   // layer-0 neighbor sums
__device__ __align__(16) float g_h1[N_NODES * HID];     // layer-0 output
__device__ __align__(16) float g_agg1[N_NODES * HID];   // layer-1 neighbor sums
__device__ float g_invdeg[N_NODES];
__device__ int   g_deg[N_NODES];
__device__ int   g_depthmax;
__device__ __align__(16) float g_pooled[N_GRAPHS * HID];
__device__ float g_cnt[N_GRAPHS];

// ---------------- packed f32x2 helpers (FFMA2: full-rate fp32 on sm_103a) --------
__device__ __forceinline__ unsigned long long dup2(float a) {
    unsigned long long r;
    asm("mov.b64 %0, {%1, %1};" : "=l"(r) : "f"(a));
    return r;
}
__device__ __forceinline__ void fma2(unsigned long long& acc, unsigned long long a,
                                     unsigned long long b) {
    asm("fma.rn.f32x2 %0, %1, %2, %0;" : "+l"(acc) : "l"(a), "l"(b));
}
__device__ __forceinline__ void unpack2(unsigned long long v, float& lo, float& hi) {
    asm("mov.b64 {%0, %1}, %2;" : "=f"(lo), "=f"(hi) : "l"(v));
}

// ---------------- K1: zero scratch ----------------
__global__ void k_zero() {
    int tid = blockIdx.x * blockDim.x + threadIdx.x;
    int stride = gridDim.x * blockDim.x;
    float4 z4 = make_float4(0.f, 0.f, 0.f, 0.f);
    float4* a0 = reinterpret_cast<float4*>(g_agg0);
    float4* a1 = reinterpret_cast<float4*>(g_agg1);
    float4* pl = reinterpret_cast<float4*>(g_pooled);
    for (int i = tid; i < N_NODES * (K0P / 4); i += stride) a0[i] = z4;
    for (int i = tid; i < N_NODES * (HID / 4); i += stride) a1[i] = z4;
    for (int i = tid; i < N_GRAPHS * (HID / 4); i += stride) pl[i] = z4;
    for (int i = tid; i < N_NODES; i += stride) g_deg[i] = 0;
    for (int i = tid; i < N_GRAPHS; i += stride) g_cnt[i] = 0.f;
    if (tid == 0) g_depthmax = 0;
}

// ---------------- K2: degree counts, depth max, graph counts ----------------
__global__ void k_stats(const int* __restrict__ edge, const int* __restrict__ depth,
                        const int* __restrict__ batch) {
    int tid = blockIdx.x * blockDim.x + threadIdx.x;
    int stride = gridDim.x * blockDim.x;
    for (int e = tid; e < N_EDGES; e += stride)
        atomicAdd(&g_deg[edge[N_EDGES + e]], 1);
    int dm = 0;
    for (int i = tid; i < N_NODES; i += stride) dm = max(dm, depth[i]);
    dm = __reduce_max_sync(0xffffffffu, dm);
    if ((threadIdx.x & 31) == 0) atomicMax(&g_depthmax, dm);
    for (int i = tid; i < N_NODES; i += stride)
        atomicAdd(&g_cnt[batch[i]], 1.0f);
}

// ---------------- K3: build node features + inv_deg (one warp per node) ---------
__global__ void k_build(const int* __restrict__ nt, const int* __restrict__ ih,
                        const float* __restrict__ flags, const int* __restrict__ depth,
                        const float* __restrict__ embn, const float* __restrict__ embi) {
    int gw = (blockIdx.x * blockDim.x + threadIdx.x) >> 5;
    int lane = threadIdx.x & 31;
    int nwarps = (gridDim.x * blockDim.x) >> 5;
    float dmaxf = fmaxf((float)g_depthmax, 1.0f);
    for (int node = gw; node < N_NODES; node += nwarps) {
        int t = nt[node], id = ih[node];
        float* row = g_x0 + node * K0P;
        row[lane]      = embn[t * 64 + lane];
        row[32 + lane] = embn[t * 64 + 32 + lane];
        row[64 + lane] = embi[id * 32 + lane];
        if (lane < 8) {
            float v = 0.f;
            if (lane < 5) v = flags[node * 5 + lane];
            else if (lane == 5) v = (float)depth[node] / dmaxf;
            row[96 + lane] = v;  // 101=depth, 102/103=pad
        }
        if (lane == 0)
            g_invdeg[node] = 1.0f / fmaxf((float)g_deg[node], 1.0f);
    }
}

// ---------------- K4/K6: edge scatter-sum (warp per edge, v4 reductions) --------
template <int LAYER>
__global__ void k_scatter(const int* __restrict__ edge) {
    const float* __restrict__ x = (LAYER == 0) ? g_x0 : g_h1;
    float* __restrict__ agg     = (LAYER == 0) ? g_agg0 : g_agg1;
    const int NV4 = (LAYER == 0) ? (K0P / 4) : (HID / 4);  // 26 or 32
    int t = blockIdx.x * blockDim.x + threadIdx.x;
    int wstride = (gridDim.x * blockDim.x) >> 5;
    int lane = t & 31;
    for (int e = t >> 5; e < N_EDGES; e += wstride) {
        if (lane < NV4) {
            int s = __ldg(&edge[e]);
            int d = __ldg(&edge[N_EDGES + e]);
            float4 v = *reinterpret_cast<const float4*>(x + s * NV4 * 4 + lane * 4);
            const float* p = agg + d * NV4 * 4 + lane * 4;
            asm volatile("red.global.add.v4.f32 [%0], {%1,%2,%3,%4};"
                         :: "l"(p), "f"(v.x), "f"(v.y), "f"(v.z), "f"(v.w)
                         : "memory");
        }
    }
}

// ---------------- K5/K7: fused SAGE layer GEMM ----------------------------------
// out = relu(A@Ws + (agg*invdeg)@Wn + bs + bn). invdeg folded into the agg smem
// tile so a single accumulator covers both matmuls. LAYER==1 pools directly.
template <int LAYER>
__global__ __launch_bounds__(256) void k_gemm(
    const float* __restrict__ Ws, const float* __restrict__ Wn,
    const float* __restrict__ bs, const float* __restrict__ bn,
    const int* __restrict__ batch) {
    const int KP = (LAYER == 0) ? K0P : HID;
    const int Kdim = (LAYER == 0) ? K0DIM : HID;
    const int KTILES = KP / 8;
    const float* __restrict__ A   = (LAYER == 0) ? g_x0 : g_h1;
    const float* __restrict__ Agg = (LAYER == 0) ? g_agg0 : g_agg1;

    __shared__ float As[8][64];
    __shared__ float Ba[8][64];
    __shared__ float Wss[8][128];
    __shared__ float Wns[8][128];

    int m0 = blockIdx.x * 64;
    int tid = threadIdx.x;
    int tx = tid & 15;   // column group: cols tx*8 .. tx*8+7
    int ty = tid >> 4;   // row group:    rows ty*4 .. ty*4+3

    unsigned long long acc[4][4];  // [row][colpair], f32x2 packed
#pragma unroll
    for (int r = 0; r < 4; r++)
#pragma unroll
        for (int cp = 0; cp < 4; cp++) acc[r][cp] = 0ull;

    for (int kt = 0; kt < KTILES; kt++) {
        int kk = kt * 8;
#pragma unroll
        for (int i = 0; i < 2; i++) {
            int idx = tid + i * 256;
            int m = idx >> 3, k = idx & 7;
            int row = m0 + m;
            float a = 0.f, b = 0.f;
            if (row < N_NODES) {
                a = A[row * KP + kk + k];
                b = Agg[row * KP + kk + k] * g_invdeg[row];
            }
            As[k][m] = a;
            Ba[k][m] = b;
        }
#pragma unroll
        for (int i = 0; i < 4; i++) {
            int idx = tid + i * 256;
            int k = idx >> 7, n = idx & 127;
            float ws = 0.f, wn = 0.f;
            if (kk + k < Kdim) {
                ws = Ws[(kk + k) * 128 + n];
                wn = Wn[(kk + k) * 128 + n];
            }
            Wss[k][n] = ws;
            Wns[k][n] = wn;
        }
        __syncthreads();
#pragma unroll
        for (int k = 0; k < 8; k++) {
            float4 a4 = *reinterpret_cast<const float4*>(&As[k][ty * 4]);
            float4 b4 = *reinterpret_cast<const float4*>(&Ba[k][ty * 4]);
            unsigned long long ad[4] = {dup2(a4.x), dup2(a4.y), dup2(a4.z), dup2(a4.w)};
            unsigned long long bd[4] = {dup2(b4.x), dup2(b4.y), dup2(b4.z), dup2(b4.w)};
            const unsigned long long* wsp =
                reinterpret_cast<const unsigned long long*>(&Wss[k][tx * 8]);
            const unsigned long long* wnp =
                reinterpret_cast<const unsigned long long*>(&Wns[k][tx * 8]);
#pragma unroll
            for (int cp = 0; cp < 4; cp++) {
                unsigned long long w2s = wsp[cp];
                unsigned long long w2n = wnp[cp];
#pragma unroll
                for (int r = 0; r < 4; r++) {
                    fma2(acc[r][cp], ad[r], w2s);
                    fma2(acc[r][cp], bd[r], w2n);
                }
            }
        }
        __syncthreads();
    }

    // epilogue
    int colbase = tx * 8;
    float bias[8];
#pragma unroll
    for (int c = 0; c < 8; c++) bias[c] = bs[colbase + c] + bn[colbase + c];

#pragma unroll
    for (int r = 0; r < 4; r++) {
        int row = m0 + ty * 4 + r;
        if (row >= N_NODES) continue;
        float v[8];
#pragma unroll
        for (int cp = 0; cp < 4; cp++) unpack2(acc[r][cp], v[2 * cp], v[2 * cp + 1]);
#pragma unroll
        for (int c = 0; c < 8; c++) v[c] = fmaxf(v[c] + bias[c], 0.f);
        if (LAYER == 0) {
            float4* o = reinterpret_cast<float4*>(g_h1 + row * HID + colbase);
            o[0] = make_float4(v[0], v[1], v[2], v[3]);
            o[1] = make_float4(v[4], v[5], v[6], v[7]);
        } else {
            int b = batch[row];
            const float* p = g_pooled + b * HID + colbase;
            asm volatile("red.global.add.v4.f32 [%0], {%1,%2,%3,%4};"
                         :: "l"(p), "f"(v[0]), "f"(v[1]), "f"(v[2]), "f"(v[3])
                         : "memory");
            asm volatile("red.global.add.v4.f32 [%0], {%1,%2,%3,%4};"
                         :: "l"(p + 4), "f"(v[4]), "f"(v[5]), "f"(v[6]), "f"(v[7])
                         : "memory");
        }
    }
}

// ---------------- K8: heads (one warp per graph) --------------------------------
__global__ void k_heads(const float* __restrict__ Wr, const float* __restrict__ br,
                        const float* __restrict__ Wc, const float* __restrict__ bc,
                        float* __restrict__ out) {
    int g = blockIdx.x;
    int lane = threadIdx.x;  // 32 threads
    float inv = 1.0f / fmaxf(g_cnt[g], 1.0f);
    float4 gv = *reinterpret_cast<const float4*>(g_pooled + g * HID + lane * 4);
    float gvals[4] = {gv.x * inv, gv.y * inv, gv.z * inv, gv.w * inv};

    // risk head
    float pr = 0.f;
#pragma unroll
    for (int i = 0; i < 4; i++) pr += gvals[i] * Wr[lane * 4 + i];
#pragma unroll
    for (int off = 16; off > 0; off >>= 1) pr += __shfl_xor_sync(0xffffffffu, pr, off);
    if (lane == 0) out[g] = pr + br[0];

    // category head
    for (int o = 0; o < NCAT; o++) {
        float p = 0.f;
#pragma unroll
        for (int i = 0; i < 4; i++) p += gvals[i] * Wc[(lane * 4 + i) * NCAT + o];
#pragma unroll
        for (int off = 16; off > 0; off >>= 1) p += __shfl_xor_sync(0xffffffffu, p, off);
        if (lane == 0) out[N_GRAPHS + g * NCAT + o] = p + bc[o];
    }
}

// ---------------- launch ----------------
extern "C" void kernel_launch(void* const* d_in, const int* in_sizes, int n_in,
                              void* d_out, int out_size) {
    const int*   node_type = (const int*)d_in[0];
    const int*   ident     = (const int*)d_in[1];
    const float* flags     = (const float*)d_in[2];
    const int*   depth     = (const int*)d_in[3];
    const int*   edge      = (const int*)d_in[4];
    const int*   batch     = (const int*)d_in[5];
    const float* emb_node  = (const float*)d_in[6];
    const float* emb_ident = (const float*)d_in[7];
    const float* Ws0 = (const float*)d_in[8];
    const float* bs0 = (const float*)d_in[9];
    const float* Wn0 = (const float*)d_in[10];
    const float* bn0 = (const float*)d_in[11];
    const float* Ws1 = (const float*)d_in[12];
    const float* bs1 = (const float*)d_in[13];
    const float* Wn1 = (const float*)d_in[14];
    const float* bn1 = (const float*)d_in[15];
    const float* Wr  = (const float*)d_in[16];
    const float* br  = (const float*)d_in[17];
    const float* Wc  = (const float*)d_in[18];
    const float* bc  = (const float*)d_in[19];
    float* out = (float*)d_out;

    k_zero<<<2048, 256>>>();
    k_stats<<<2048, 256>>>(edge, depth, batch);
    k_build<<<2048, 256>>>(node_type, ident, flags, depth, emb_node, emb_ident);
    k_scatter<0><<<8192, 256>>>(edge);
    k_gemm<0><<<(N_NODES + 63) / 64, 256>>>(Ws0, Wn0, bs0, bn0, batch);
    k_scatter<1><<<8192, 256>>>(edge);
    k_gemm<1><<<(N_NODES + 63) / 64, 256>>>(Ws1, Wn1, bs1, bn1, batch);
    k_heads<<<N_GRAPHS, 32>>>(Wr, br, Wc, bc, out);
}

// round 2
// speedup vs baseline: 1.3200x; 1.3200x over previous
#include <cuda_runtime.h>

#define N_NODES 100000
#define N_EDGES 1600000
#define N_GRAPHS 512
#define HID 128
#define NCAT 10
#define NT_ROWS 258      // NODE_TYPE_BUCKETS + 2
#define ID_ROWS 50002    // IDENT_BUCKETS + 2

// ---------------- scratch (device globals; no runtime allocation) ----------------
__device__ __align__(16) float g_TNs[NT_ROWS * HID];   // emb_node @ Ws0[0:64]
__device__ __align__(16) float g_TNn[NT_ROWS * HID];   // emb_node @ Wn0[0:64]
__device__ __align__(16) float g_TIs[ID_ROWS * HID];   // emb_ident @ Ws0[64:96]
__device__ __align__(16) float g_TIn[ID_ROWS * HID];   // emb_ident @ Wn0[64:96]
__device__ __align__(16) float g_self0[N_NODES * HID]; // x0 @ Ws0 (no bias)
__device__ __align__(16) float g_y0[N_NODES * HID];    // x0 @ Wn0 (no bias)
__device__ __align__(16) float g_h1[N_NODES * HID];    // layer-0 output
__device__ __align__(16) float g_u1[N_NODES * HID];    // h1 @ Ws1 (no bias)
__device__ __align__(16) float g_z1[N_NODES * HID];    // h1 @ Wn1 (no bias)
__device__ int   g_deg[N_NODES];
__device__ int   g_off[N_NODES];
__device__ int   g_cursor[N_NODES];
__device__ int   g_ssrc[N_EDGES];                      // src ids sorted by dst
__device__ float g_invdeg[N_NODES];
__device__ int   g_depthmax;
__device__ __align__(16) float g_pooled[N_GRAPHS * HID];
__device__ float g_cnt[N_GRAPHS];

// ---------------- packed f32x2 helpers (FFMA2: full-rate fp32 on sm_103a) --------
__device__ __forceinline__ unsigned long long dup2(float a) {
    unsigned long long r;
    asm("mov.b64 %0, {%1, %1};" : "=l"(r) : "f"(a));
    return r;
}
__device__ __forceinline__ void fma2(unsigned long long& acc, unsigned long long a,
                                     unsigned long long b) {
    asm("fma.rn.f32x2 %0, %1, %2, %0;" : "+l"(acc) : "l"(a), "l"(b));
}
__device__ __forceinline__ void unpack2(unsigned long long v, float& lo, float& hi) {
    asm("mov.b64 {%0, %1}, %2;" : "=f"(lo), "=f"(hi) : "l"(v));
}
__device__ __forceinline__ float4 ld4(const float* p) {
    return *reinterpret_cast<const float4*>(p);
}
__device__ __forceinline__ void add4(float4& a, float4 b) {
    a.x += b.x; a.y += b.y; a.z += b.z; a.w += b.w;
}
__device__ __forceinline__ void fma4(float4& a, float s, float4 b) {
    a.x += s * b.x; a.y += s * b.y; a.z += s * b.z; a.w += s * b.w;
}
__device__ __forceinline__ void red4(const float* p, float4 v) {
    asm volatile("red.global.add.v4.f32 [%0], {%1,%2,%3,%4};"
                 :: "l"(p), "f"(v.x), "f"(v.y), "f"(v.z), "f"(v.w) : "memory");
}

// ---------------- K1: zero the small state -------------------------------------
__global__ void k_zero() {
    int tid = blockIdx.x * blockDim.x + threadIdx.x;
    int stride = gridDim.x * blockDim.x;
    for (int i = tid; i < N_NODES; i += stride) { g_deg[i] = 0; g_cursor[i] = 0; }
    for (int i = tid; i < N_GRAPHS * HID; i += stride) g_pooled[i] = 0.f;
    for (int i = tid; i < N_GRAPHS; i += stride) g_cnt[i] = 0.f;
    if (tid == 0) g_depthmax = 0;
}

// ---------------- K2: degree counts, depth max, graph counts --------------------
__global__ void k_stats(const int* __restrict__ edge, const int* __restrict__ depth,
                        const int* __restrict__ batch) {
    int tid = blockIdx.x * blockDim.x + threadIdx.x;
    int stride = gridDim.x * blockDim.x;
    for (int e = tid; e < N_EDGES; e += stride)
        atomicAdd(&g_deg[edge[N_EDGES + e]], 1);
    int dm = 0;
    for (int i = tid; i < N_NODES; i += stride) dm = max(dm, depth[i]);
    dm = __reduce_max_sync(0xffffffffu, dm);
    if ((threadIdx.x & 31) == 0) atomicMax(&g_depthmax, dm);
    for (int i = tid; i < N_NODES; i += stride)
        atomicAdd(&g_cnt[batch[i]], 1.0f);
}

// ---------------- K3: exclusive scan of degrees (single block) ------------------
__global__ void k_scan() {
    __shared__ int wsum[32];
    int tid = threadIdx.x, lane = tid & 31, wid = tid >> 5;
    int base = 0;
    for (int start = 0; start < N_NODES; start += 1024) {
        int i = start + tid;
        int v = (i < N_NODES) ? g_deg[i] : 0;
        int x = v;
#pragma unroll
        for (int o = 1; o < 32; o <<= 1) {
            int y = __shfl_up_sync(0xffffffffu, x, o);
            if (lane >= o) x += y;
        }
        if (lane == 31) wsum[wid] = x;
        __syncthreads();
        if (wid == 0) {
            int s = wsum[lane];
#pragma unroll
            for (int o = 1; o < 32; o <<= 1) {
                int y = __shfl_up_sync(0xffffffffu, s, o);
                if (lane >= o) s += y;
            }
            wsum[lane] = s;
        }
        __syncthreads();
        int pre = (wid > 0) ? wsum[wid - 1] : 0;
        if (i < N_NODES) g_off[i] = base + pre + x - v;
        base += wsum[31];
        __syncthreads();
    }
}

// ---------------- K4: bucket edges by destination -------------------------------
__global__ void k_sortedges(const int* __restrict__ edge) {
    int tid = blockIdx.x * blockDim.x + threadIdx.x;
    int stride = gridDim.x * blockDim.x;
    for (int e = tid; e < N_EDGES; e += stride) {
        int s = edge[e];
        int d = edge[N_EDGES + e];
        int p = atomicAdd(&g_cursor[d], 1);
        g_ssrc[g_off[d] + p] = s;
    }
}

// ---------------- K5: ident embedding tables (K=32 GEMM into 50002x128 x2) ------
__global__ __launch_bounds__(256) void k_table_id(const float* __restrict__ embi,
                                                  const float* __restrict__ Ws0,
                                                  const float* __restrict__ Wn0) {
    __shared__ float sW[32][128];
    __shared__ float nW[32][128];
    int tid = threadIdx.x;
    for (int i = tid; i < 32 * 128; i += 256) {
        int k = i >> 7, n = i & 127;
        sW[k][n] = Ws0[(64 + k) * 128 + n];
        nW[k][n] = Wn0[(64 + k) * 128 + n];
    }
    __syncthreads();
    int lane = tid & 31;
    int gw = (blockIdx.x * 256 + tid) >> 5;
    int nwarps = (gridDim.x * 256) >> 5;
    for (int r = gw; r < ID_ROWS; r += nwarps) {
        float me = embi[r * 32 + lane];
        unsigned long long as0 = 0, as1 = 0, an0 = 0, an1 = 0;
#pragma unroll
        for (int k = 0; k < 32; k++) {
            float e = __shfl_sync(0xffffffffu, me, k);
            unsigned long long e2 = dup2(e);
            const unsigned long long* ps =
                reinterpret_cast<const unsigned long long*>(&sW[k][lane * 4]);
            const unsigned long long* pn =
                reinterpret_cast<const unsigned long long*>(&nW[k][lane * 4]);
            fma2(as0, e2, ps[0]); fma2(as1, e2, ps[1]);
            fma2(an0, e2, pn[0]); fma2(an1, e2, pn[1]);
        }
        float v0, v1, v2, v3;
        unpack2(as0, v0, v1); unpack2(as1, v2, v3);
        *reinterpret_cast<float4*>(g_TIs + r * 128 + lane * 4) = make_float4(v0, v1, v2, v3);
        unpack2(an0, v0, v1); unpack2(an1, v2, v3);
        *reinterpret_cast<float4*>(g_TIn + r * 128 + lane * 4) = make_float4(v0, v1, v2, v3);
    }
}

// ---------------- K6: node-type embedding tables (K=64, 258 rows) ---------------
__global__ void k_table_node(const float* __restrict__ embn,
                             const float* __restrict__ Ws0,
                             const float* __restrict__ Wn0) {
    int tid = threadIdx.x;
    int lane = tid & 31;
    int gw = (blockIdx.x * 256 + tid) >> 5;
    int nwarps = (gridDim.x * 256) >> 5;
    for (int r = gw; r < NT_ROWS; r += nwarps) {
        float me0 = embn[r * 64 + lane];
        float me1 = embn[r * 64 + 32 + lane];
        float4 as = make_float4(0, 0, 0, 0), an = make_float4(0, 0, 0, 0);
#pragma unroll
        for (int k = 0; k < 64; k++) {
            float e = (k < 32) ? __shfl_sync(0xffffffffu, me0, k)
                               : __shfl_sync(0xffffffffu, me1, k - 32);
            float4 ws = ld4(Ws0 + k * 128 + lane * 4);
            float4 wn = ld4(Wn0 + k * 128 + lane * 4);
            fma4(as, e, ws);
            fma4(an, e, wn);
        }
        *reinterpret_cast<float4*>(g_TNs + r * 128 + lane * 4) = as;
        *reinterpret_cast<float4*>(g_TNn + r * 128 + lane * 4) = an;
    }
}

// ---------------- K7: per-node transformed features (self0, y0, invdeg) ---------
__global__ void k_nodefeat(const int* __restrict__ nt, const int* __restrict__ ih,
                           const float* __restrict__ flags, const int* __restrict__ depth,
                           const float* __restrict__ Ws0, const float* __restrict__ Wn0) {
    int tid = threadIdx.x;
    int lane = tid & 31;
    int gw = (blockIdx.x * 256 + tid) >> 5;
    int nwarps = (gridDim.x * 256) >> 5;
    float inv_dmax = 1.0f / fmaxf((float)g_depthmax, 1.0f);
    int c4 = lane * 4;
    for (int i = gw; i < N_NODES; i += nwarps) {
        int t = nt[i], id = ih[i];
        float4 s = ld4(g_TNs + t * 128 + c4);
        add4(s, ld4(g_TIs + id * 128 + c4));
        float4 y = ld4(g_TNn + t * 128 + c4);
        add4(y, ld4(g_TIn + id * 128 + c4));
        float dn = (float)depth[i] * inv_dmax;
#pragma unroll
        for (int j = 0; j < 5; j++) {
            float f = __ldg(&flags[i * 5 + j]);
            fma4(s, f, ld4(Ws0 + (96 + j) * 128 + c4));
            fma4(y, f, ld4(Wn0 + (96 + j) * 128 + c4));
        }
        fma4(s, dn, ld4(Ws0 + 101 * 128 + c4));
        fma4(y, dn, ld4(Wn0 + 101 * 128 + c4));
        *reinterpret_cast<float4*>(g_self0 + i * 128 + c4) = s;
        *reinterpret_cast<float4*>(g_y0 + i * 128 + c4) = y;
        if (lane == 0) g_invdeg[i] = 1.0f / fmaxf((float)g_deg[i], 1.0f);
    }
}

// ---------------- K8/K10: atomic-free aggregation + fused epilogue --------------
// warp per node: acc = sum over sorted in-edges of x[src]; then
// v = relu(base[d] + invdeg*acc + b1 + b2). LAYER 0 stores h1; LAYER 1 pools.
template <int LAYER>
__global__ __launch_bounds__(256) void k_agg(const int* __restrict__ batch,
                                             const float* __restrict__ b1,
                                             const float* __restrict__ b2) {
    const float* __restrict__ x    = (LAYER == 0) ? g_y0 : g_z1;
    const float* __restrict__ base = (LAYER == 0) ? g_self0 : g_u1;
    int tid = threadIdx.x;
    int lane = tid & 31;
    int d = blockIdx.x * 8 + (tid >> 5);
    if (d >= N_NODES) return;
    int c4 = lane * 4;
    int beg = g_off[d];
    int end = beg + g_deg[d];
    float4 a0 = make_float4(0, 0, 0, 0), a1 = a0, a2 = a0, a3 = a0;
    int k = beg;
    for (; k + 4 <= end; k += 4) {
        int s0 = __ldg(&g_ssrc[k]);
        int s1 = __ldg(&g_ssrc[k + 1]);
        int s2 = __ldg(&g_ssrc[k + 2]);
        int s3 = __ldg(&g_ssrc[k + 3]);
        add4(a0, ld4(x + s0 * 128 + c4));
        add4(a1, ld4(x + s1 * 128 + c4));
        add4(a2, ld4(x + s2 * 128 + c4));
        add4(a3, ld4(x + s3 * 128 + c4));
    }
    for (; k < end; k++) {
        int s = __ldg(&g_ssrc[k]);
        add4(a0, ld4(x + s * 128 + c4));
    }
    add4(a0, a1); add4(a2, a3); add4(a0, a2);
    float inv = g_invdeg[d];
    float4 v = ld4(base + d * 128 + c4);
    fma4(v, inv, a0);
    float4 bias1 = __ldg(reinterpret_cast<const float4*>(b1 + c4));
    float4 bias2 = __ldg(reinterpret_cast<const float4*>(b2 + c4));
    v.x = fmaxf(v.x + bias1.x + bias2.x, 0.f);
    v.y = fmaxf(v.y + bias1.y + bias2.y, 0.f);
    v.z = fmaxf(v.z + bias1.z + bias2.z, 0.f);
    v.w = fmaxf(v.w + bias1.w + bias2.w, 0.f);
    if (LAYER == 0) {
        *reinterpret_cast<float4*>(g_h1 + d * 128 + c4) = v;
    } else {
        int g = __ldg(&batch[d]);
        red4(g_pooled + g * 128 + c4, v);
    }
}

// ---------------- K9: dual-B GEMM: u1 = h1@Ws1, z1 = h1@Wn1 ---------------------
__global__ __launch_bounds__(256) void k_gemm1(const float* __restrict__ Ws,
                                               const float* __restrict__ Wn) {
    __shared__ float As[8][64];
    __shared__ float Wss[8][128];
    __shared__ float Wns[8][128];
    int m0 = blockIdx.x * 64;
    int tid = threadIdx.x;
    int tx = tid & 15;
    int ty = tid >> 4;

    unsigned long long aS[4][4], aN[4][4];
#pragma unroll
    for (int r = 0; r < 4; r++)
#pragma unroll
        for (int cp = 0; cp < 4; cp++) { aS[r][cp] = 0ull; aN[r][cp] = 0ull; }

    for (int kt = 0; kt < 16; kt++) {
        int kk = kt * 8;
#pragma unroll
        for (int i = 0; i < 2; i++) {
            int idx = tid + i * 256;
            int m = idx >> 3, k = idx & 7;
            int row = m0 + m;
            As[k][m] = (row < N_NODES) ? g_h1[row * 128 + kk + k] : 0.f;
        }
#pragma unroll
        for (int i = 0; i < 4; i++) {
            int idx = tid + i * 256;
            int k = idx >> 7, n = idx & 127;
            Wss[k][n] = Ws[(kk + k) * 128 + n];
            Wns[k][n] = Wn[(kk + k) * 128 + n];
        }
        __syncthreads();
#pragma unroll
        for (int k = 0; k < 8; k++) {
            float4 a4 = *reinterpret_cast<const float4*>(&As[k][ty * 4]);
            unsigned long long ad[4] = {dup2(a4.x), dup2(a4.y), dup2(a4.z), dup2(a4.w)};
            const unsigned long long* wsp =
                reinterpret_cast<const unsigned long long*>(&Wss[k][tx * 8]);
            const unsigned long long* wnp =
                reinterpret_cast<const unsigned long long*>(&Wns[k][tx * 8]);
#pragma unroll
            for (int cp = 0; cp < 4; cp++) {
                unsigned long long w2s = wsp[cp];
                unsigned long long w2n = wnp[cp];
#pragma unroll
                for (int r = 0; r < 4; r++) {
                    fma2(aS[r][cp], ad[r], w2s);
                    fma2(aN[r][cp], ad[r], w2n);
                }
            }
        }
        __syncthreads();
    }

    int colbase = tx * 8;
#pragma unroll
    for (int r = 0; r < 4; r++) {
        int row = m0 + ty * 4 + r;
        if (row >= N_NODES) continue;
        float v[8];
#pragma unroll
        for (int cp = 0; cp < 4; cp++) unpack2(aS[r][cp], v[2 * cp], v[2 * cp + 1]);
        float4* o = reinterpret_cast<float4*>(g_u1 + row * 128 + colbase);
        o[0] = make_float4(v[0], v[1], v[2], v[3]);
        o[1] = make_float4(v[4], v[5], v[6], v[7]);
#pragma unroll
        for (int cp = 0; cp < 4; cp++) unpack2(aN[r][cp], v[2 * cp], v[2 * cp + 1]);
        float4* o2 = reinterpret_cast<float4*>(g_z1 + row * 128 + colbase);
        o2[0] = make_float4(v[0], v[1], v[2], v[3]);
        o2[1] = make_float4(v[4], v[5], v[6], v[7]);
    }
}

// ---------------- K11: heads (one warp per graph) -------------------------------
__global__ void k_heads(const float* __restrict__ Wr, const float* __restrict__ br,
                        const float* __restrict__ Wc, const float* __restrict__ bc,
                        float* __restrict__ out) {
    int g = blockIdx.x;
    int lane = threadIdx.x;
    float inv = 1.0f / fmaxf(g_cnt[g], 1.0f);
    float4 gv = *reinterpret_cast<const float4*>(g_pooled + g * HID + lane * 4);
    float gvals[4] = {gv.x * inv, gv.y * inv, gv.z * inv, gv.w * inv};

    float pr = 0.f;
#pragma unroll
    for (int i = 0; i < 4; i++) pr += gvals[i] * Wr[lane * 4 + i];
#pragma unroll
    for (int off = 16; off > 0; off >>= 1) pr += __shfl_xor_sync(0xffffffffu, pr, off);
    if (lane == 0) out[g] = pr + br[0];

    for (int o = 0; o < NCAT; o++) {
        float p = 0.f;
#pragma unroll
        for (int i = 0; i < 4; i++) p += gvals[i] * Wc[(lane * 4 + i) * NCAT + o];
#pragma unroll
        for (int off = 16; off > 0; off >>= 1) p += __shfl_xor_sync(0xffffffffu, p, off);
        if (lane == 0) out[N_GRAPHS + g * NCAT + o] = p + bc[o];
    }
}

// ---------------- launch ----------------
extern "C" void kernel_launch(void* const* d_in, const int* in_sizes, int n_in,
                              void* d_out, int out_size) {
    const int*   node_type = (const int*)d_in[0];
    const int*   ident     = (const int*)d_in[1];
    const float* flags     = (const float*)d_in[2];
    const int*   depth     = (const int*)d_in[3];
    const int*   edge      = (const int*)d_in[4];
    const int*   batch     = (const int*)d_in[5];
    const float* emb_node  = (const float*)d_in[6];
    const float* emb_ident = (const float*)d_in[7];
    const float* Ws0 = (const float*)d_in[8];
    const float* bs0 = (const float*)d_in[9];
    const float* Wn0 = (const float*)d_in[10];
    const float* bn0 = (const float*)d_in[11];
    const float* Ws1 = (const float*)d_in[12];
    const float* bs1 = (const float*)d_in[13];
    const float* Wn1 = (const float*)d_in[14];
    const float* bn1 = (const float*)d_in[15];
    const float* Wr  = (const float*)d_in[16];
    const float* br  = (const float*)d_in[17];
    const float* Wc  = (const float*)d_in[18];
    const float* bc  = (const float*)d_in[19];
    float* out = (float*)d_out;

    k_zero<<<512, 256>>>();
    k_stats<<<2048, 256>>>(edge, depth, batch);
    k_scan<<<1, 1024>>>();
    k_sortedges<<<2048, 256>>>(edge);
    k_table_id<<<2048, 256>>>(emb_ident, Ws0, Wn0);
    k_table_node<<<33, 256>>>(emb_node, Ws0, Wn0);
    k_nodefeat<<<2048, 256>>>(node_type, ident, flags, depth, Ws0, Wn0);
    k_agg<0><<<(N_NODES + 7) / 8, 256>>>(batch, bs0, bn0);
    k_gemm1<<<(N_NODES + 63) / 64, 256>>>(Ws1, Wn1);
    k_agg<1><<<(N_NODES + 7) / 8, 256>>>(batch, bs1, bn1);
    k_heads<<<N_GRAPHS, 32>>>(Wr, br, Wc, bc, out);
}

// round 5
// speedup vs baseline: 1.3286x; 1.0065x over previous
#include <cuda_runtime.h>
#include <cuda_fp16.h>
#include <cstdint>

#define N_NODES 100000
#define N_EDGES 1600000
#define N_GRAPHS 512
#define HID 128
#define NCAT 10
#define NT_ROWS 258      // NODE_TYPE_BUCKETS + 2
#define ID_ROWS 50002    // IDENT_BUCKETS + 2

// ---------------- scratch (device globals; no runtime allocation) ----------------
__device__ __align__(16) float g_TNs[NT_ROWS * HID];    // emb_node @ Ws0[0:64]
__device__ __align__(16) float g_TNn[NT_ROWS * HID];    // emb_node @ Wn0[0:64]
__device__ __align__(16) float g_TIs[ID_ROWS * HID];    // emb_ident @ Ws0[64:96]
__device__ __align__(16) float g_TIn[ID_ROWS * HID];    // emb_ident @ Wn0[64:96]
__device__ __align__(16) float  g_self0[N_NODES * HID]; // x0 @ Ws0 (no bias)
__device__ __align__(16) __half g_y0h[N_NODES * HID];   // x0 @ Wn0 (fp16, gather operand)
__device__ __align__(16) float  g_h1[N_NODES * HID];    // layer-0 output (GEMM A)
__device__ __align__(16) __half g_h1h[N_NODES * HID];   // layer-0 output (fp16 gather)
__device__ __align__(16) float  g_agg1[N_NODES * HID];  // sum of h1 over in-edges
__device__ int   g_deg[N_NODES];
__device__ int   g_off[N_NODES];
__device__ int   g_cursor[N_NODES];
__device__ int   g_ssrc[N_EDGES];                       // src ids sorted by dst
__device__ float g_invdeg[N_NODES];
__device__ int   g_depthmax;
__device__ __align__(16) float g_pooled[N_GRAPHS * HID];
__device__ float g_cnt[N_GRAPHS];

// ---------------- helpers --------------------------------------------------------
__device__ __forceinline__ unsigned long long dup2(float a) {
    unsigned long long r;
    asm("mov.b64 %0, {%1, %1};" : "=l"(r) : "f"(a));
    return r;
}
__device__ __forceinline__ void fma2(unsigned long long& acc, unsigned long long a,
                                     unsigned long long b) {
    asm("fma.rn.f32x2 %0, %1, %2, %0;" : "+l"(acc) : "l"(a), "l"(b));
}
__device__ __forceinline__ void unpack2(unsigned long long v, float& lo, float& hi) {
    asm("mov.b64 {%0, %1}, %2;" : "=f"(lo), "=f"(hi) : "l"(v));
}
__device__ __forceinline__ float4 ld4(const float* p) {
    return *reinterpret_cast<const float4*>(p);
}
__device__ __forceinline__ void add4(float4& a, float4 b) {
    a.x += b.x; a.y += b.y; a.z += b.z; a.w += b.w;
}
__device__ __forceinline__ void fma4(float4& a, float s, float4 b) {
    a.x += s * b.x; a.y += s * b.y; a.z += s * b.z; a.w += s * b.w;
}
__device__ __forceinline__ void red4(const float* p, float4 v) {
    asm volatile("red.global.add.v4.f32 [%0], {%1,%2,%3,%4};"
                 :: "l"(p), "f"(v.x), "f"(v.y), "f"(v.z), "f"(v.w) : "memory");
}
// load 4 halves (8 bytes) and accumulate into float4
__device__ __forceinline__ void hacc4(float4& a, const __half* p) {
    uint2 u = *reinterpret_cast<const uint2*>(p);
    __half2 h0 = *reinterpret_cast<const __half2*>(&u.x);
    __half2 h1 = *reinterpret_cast<const __half2*>(&u.y);
    float2 f0 = __half22float2(h0);
    float2 f1 = __half22float2(h1);
    a.x += f0.x; a.y += f0.y; a.z += f1.x; a.w += f1.y;
}
__device__ __forceinline__ void st4h(__half* p, float4 v) {
    __half2 h0 = __floats2half2_rn(v.x, v.y);
    __half2 h1 = __floats2half2_rn(v.z, v.w);
    uint2 u;
    u.x = *reinterpret_cast<const uint32_t*>(&h0);
    u.y = *reinterpret_cast<const uint32_t*>(&h1);
    *reinterpret_cast<uint2*>(p) = u;
}

// ---------------- K1: zero small state -------------------------------------------
__global__ void k_zero() {
    int tid = blockIdx.x * blockDim.x + threadIdx.x;
    int stride = gridDim.x * blockDim.x;
    for (int i = tid; i < N_NODES; i += stride) { g_deg[i] = 0; g_cursor[i] = 0; }
    for (int i = tid; i < N_GRAPHS * HID; i += stride) g_pooled[i] = 0.f;
    for (int i = tid; i < N_GRAPHS; i += stride) g_cnt[i] = 0.f;
    if (tid == 0) g_depthmax = 0;
}

// ---------------- K2: degrees, depth max, graph counts ----------------------------
__global__ void k_stats(const int* __restrict__ edge, const int* __restrict__ depth,
                        const int* __restrict__ batch) {
    int tid = blockIdx.x * blockDim.x + threadIdx.x;
    int stride = gridDim.x * blockDim.x;
    for (int e = tid; e < N_EDGES; e += stride)
        atomicAdd(&g_deg[edge[N_EDGES + e]], 1);
    int dm = 0;
    for (int i = tid; i < N_NODES; i += stride) dm = max(dm, depth[i]);
    dm = __reduce_max_sync(0xffffffffu, dm);
    if ((threadIdx.x & 31) == 0) atomicMax(&g_depthmax, dm);
    for (int i = tid; i < N_NODES; i += stride)
        atomicAdd(&g_cnt[batch[i]], 1.0f);
}

// ---------------- K3: exclusive scan of degrees (single block) --------------------
__global__ void k_scan() {
    __shared__ int wsum[32];
    int tid = threadIdx.x, lane = tid & 31, wid = tid >> 5;
    int base = 0;
    for (int start = 0; start < N_NODES; start += 1024) {
        int i = start + tid;
        int v = (i < N_NODES) ? g_deg[i] : 0;
        int x = v;
#pragma unroll
        for (int o = 1; o < 32; o <<= 1) {
            int y = __shfl_up_sync(0xffffffffu, x, o);
            if (lane >= o) x += y;
        }
        if (lane == 31) wsum[wid] = x;
        __syncthreads();
        if (wid == 0) {
            int s = wsum[lane];
#pragma unroll
            for (int o = 1; o < 32; o <<= 1) {
                int y = __shfl_up_sync(0xffffffffu, s, o);
                if (lane >= o) s += y;
            }
            wsum[lane] = s;
        }
        __syncthreads();
        int pre = (wid > 0) ? wsum[wid - 1] : 0;
        if (i < N_NODES) g_off[i] = base + pre + x - v;
        base += wsum[31];
        __syncthreads();
    }
}

// ---------------- K4: bucket edges by destination ---------------------------------
__global__ void k_sortedges(const int* __restrict__ edge) {
    int tid = blockIdx.x * blockDim.x + threadIdx.x;
    int stride = gridDim.x * blockDim.x;
    for (int e = tid; e < N_EDGES; e += stride) {
        int s = edge[e];
        int d = edge[N_EDGES + e];
        int p = atomicAdd(&g_cursor[d], 1);
        g_ssrc[g_off[d] + p] = s;
    }
}

// ---------------- K5: ident embedding tables --------------------------------------
__global__ __launch_bounds__(256) void k_table_id(const float* __restrict__ embi,
                                                  const float* __restrict__ Ws0,
                                                  const float* __restrict__ Wn0) {
    __shared__ float sW[32][128];
    __shared__ float nW[32][128];
    int tid = threadIdx.x;
    for (int i = tid; i < 32 * 128; i += 256) {
        int k = i >> 7, n = i & 127;
        sW[k][n] = Ws0[(64 + k) * 128 + n];
        nW[k][n] = Wn0[(64 + k) * 128 + n];
    }
    __syncthreads();
    int lane = tid & 31;
    int gw = (blockIdx.x * 256 + tid) >> 5;
    int nwarps = (gridDim.x * 256) >> 5;
    for (int r = gw; r < ID_ROWS; r += nwarps) {
        float me = embi[r * 32 + lane];
        unsigned long long as0 = 0, as1 = 0, an0 = 0, an1 = 0;
#pragma unroll
        for (int k = 0; k < 32; k++) {
            float e = __shfl_sync(0xffffffffu, me, k);
            unsigned long long e2 = dup2(e);
            const unsigned long long* ps =
                reinterpret_cast<const unsigned long long*>(&sW[k][lane * 4]);
            const unsigned long long* pn =
                reinterpret_cast<const unsigned long long*>(&nW[k][lane * 4]);
            fma2(as0, e2, ps[0]); fma2(as1, e2, ps[1]);
            fma2(an0, e2, pn[0]); fma2(an1, e2, pn[1]);
        }
        float v0, v1, v2, v3;
        unpack2(as0, v0, v1); unpack2(as1, v2, v3);
        *reinterpret_cast<float4*>(g_TIs + r * 128 + lane * 4) = make_float4(v0, v1, v2, v3);
        unpack2(an0, v0, v1); unpack2(an1, v2, v3);
        *reinterpret_cast<float4*>(g_TIn + r * 128 + lane * 4) = make_float4(v0, v1, v2, v3);
    }
}

// ---------------- K6: node-type embedding tables ----------------------------------
__global__ void k_table_node(const float* __restrict__ embn,
                             const float* __restrict__ Ws0,
                             const float* __restrict__ Wn0) {
    int tid = threadIdx.x;
    int lane = tid & 31;
    int gw = (blockIdx.x * 256 + tid) >> 5;
    int nwarps = (gridDim.x * 256) >> 5;
    for (int r = gw; r < NT_ROWS; r += nwarps) {
        float me0 = embn[r * 64 + lane];
        float me1 = embn[r * 64 + 32 + lane];
        float4 as = make_float4(0, 0, 0, 0), an = make_float4(0, 0, 0, 0);
#pragma unroll
        for (int k = 0; k < 64; k++) {
            float e = (k < 32) ? __shfl_sync(0xffffffffu, me0, k)
                               : __shfl_sync(0xffffffffu, me1, k - 32);
            float4 ws = ld4(Ws0 + k * 128 + lane * 4);
            float4 wn = ld4(Wn0 + k * 128 + lane * 4);
            fma4(as, e, ws);
            fma4(an, e, wn);
        }
        *reinterpret_cast<float4*>(g_TNs + r * 128 + lane * 4) = as;
        *reinterpret_cast<float4*>(g_TNn + r * 128 + lane * 4) = an;
    }
}

// ---------------- K7: per-node transformed features (self0 f32, y0 fp16) ---------
__global__ void k_nodefeat(const int* __restrict__ nt, const int* __restrict__ ih,
                           const float* __restrict__ flags, const int* __restrict__ depth,
                           const float* __restrict__ Ws0, const float* __restrict__ Wn0) {
    int tid = threadIdx.x;
    int lane = tid & 31;
    int gw = (blockIdx.x * 256 + tid) >> 5;
    int nwarps = (gridDim.x * 256) >> 5;
    float inv_dmax = 1.0f / fmaxf((float)g_depthmax, 1.0f);
    int c4 = lane * 4;
    for (int i = gw; i < N_NODES; i += nwarps) {
        int t = nt[i], id = ih[i];
        float4 s = ld4(g_TNs + t * 128 + c4);
        add4(s, ld4(g_TIs + id * 128 + c4));
        float4 y = ld4(g_TNn + t * 128 + c4);
        add4(y, ld4(g_TIn + id * 128 + c4));
        float dn = (float)depth[i] * inv_dmax;
#pragma unroll
        for (int j = 0; j < 5; j++) {
            float f = __ldg(&flags[i * 5 + j]);
            fma4(s, f, ld4(Ws0 + (96 + j) * 128 + c4));
            fma4(y, f, ld4(Wn0 + (96 + j) * 128 + c4));
        }
        fma4(s, dn, ld4(Ws0 + 101 * 128 + c4));
        fma4(y, dn, ld4(Wn0 + 101 * 128 + c4));
        *reinterpret_cast<float4*>(g_self0 + i * 128 + c4) = s;
        st4h(g_y0h + i * 128 + c4, y);
        if (lane == 0) g_invdeg[i] = 1.0f / fmaxf((float)g_deg[i], 1.0f);
    }
}

// ---------------- K8: layer-0 aggregation (fp16 gather) + fused epilogue ---------
// warp per node: acc = sum y0h[src]; h1 = relu(self0 + invdeg*acc + bs0 + bn0);
// store h1 (fp32 for GEMM) and h1h (fp16 for layer-1 gather).
__global__ __launch_bounds__(256) void k_agg0(const float* __restrict__ b1,
                                              const float* __restrict__ b2) {
    int tid = threadIdx.x;
    int lane = tid & 31;
    int d = blockIdx.x * 8 + (tid >> 5);
    if (d >= N_NODES) return;
    int c4 = lane * 4;
    int beg = g_off[d];
    int end = beg + g_deg[d];
    float4 a0 = make_float4(0, 0, 0, 0), a1 = a0, a2 = a0, a3 = a0;
    int k = beg;
    for (; k + 4 <= end; k += 4) {
        int s0 = __ldg(&g_ssrc[k]);
        int s1 = __ldg(&g_ssrc[k + 1]);
        int s2 = __ldg(&g_ssrc[k + 2]);
        int s3 = __ldg(&g_ssrc[k + 3]);
        hacc4(a0, g_y0h + s0 * 128 + c4);
        hacc4(a1, g_y0h + s1 * 128 + c4);
        hacc4(a2, g_y0h + s2 * 128 + c4);
        hacc4(a3, g_y0h + s3 * 128 + c4);
    }
    for (; k < end; k++) {
        int s = __ldg(&g_ssrc[k]);
        hacc4(a0, g_y0h + s * 128 + c4);
    }
    add4(a0, a1); add4(a2, a3); add4(a0, a2);
    float inv = g_invdeg[d];
    float4 v = ld4(g_self0 + d * 128 + c4);
    fma4(v, inv, a0);
    float4 bias1 = __ldg(reinterpret_cast<const float4*>(b1 + c4));
    float4 bias2 = __ldg(reinterpret_cast<const float4*>(b2 + c4));
    v.x = fmaxf(v.x + bias1.x + bias2.x, 0.f);
    v.y = fmaxf(v.y + bias1.y + bias2.y, 0.f);
    v.z = fmaxf(v.z + bias1.z + bias2.z, 0.f);
    v.w = fmaxf(v.w + bias1.w + bias2.w, 0.f);
    *reinterpret_cast<float4*>(g_h1 + d * 128 + c4) = v;
    st4h(g_h1h + d * 128 + c4, v);
}

// ---------------- K9: layer-1 aggregation (fp16 gather of h1) --------------------
__global__ __launch_bounds__(256) void k_agg1() {
    int tid = threadIdx.x;
    int lane = tid & 31;
    int d = blockIdx.x * 8 + (tid >> 5);
    if (d >= N_NODES) return;
    int c4 = lane * 4;
    int beg = g_off[d];
    int end = beg + g_deg[d];
    float4 a0 = make_float4(0, 0, 0, 0), a1 = a0, a2 = a0, a3 = a0;
    int k = beg;
    for (; k + 4 <= end; k += 4) {
        int s0 = __ldg(&g_ssrc[k]);
        int s1 = __ldg(&g_ssrc[k + 1]);
        int s2 = __ldg(&g_ssrc[k + 2]);
        int s3 = __ldg(&g_ssrc[k + 3]);
        hacc4(a0, g_h1h + s0 * 128 + c4);
        hacc4(a1, g_h1h + s1 * 128 + c4);
        hacc4(a2, g_h1h + s2 * 128 + c4);
        hacc4(a3, g_h1h + s3 * 128 + c4);
    }
    for (; k < end; k++) {
        int s = __ldg(&g_ssrc[k]);
        hacc4(a0, g_h1h + s * 128 + c4);
    }
    add4(a0, a1); add4(a2, a3); add4(a0, a2);
    *reinterpret_cast<float4*>(g_agg1 + d * 128 + c4) = a0;
}

// ---------------- K10: fused dual-GEMM + bias + relu + pool ----------------------
// v = relu(h1@Ws1 + (agg1*invdeg)@Wn1 + bs1 + bn1); red-atomics into g_pooled.
__global__ __launch_bounds__(256) void k_gemm1(
    const float* __restrict__ Ws, const float* __restrict__ Wn,
    const float* __restrict__ bs, const float* __restrict__ bn,
    const int* __restrict__ batch) {
    __shared__ float As[8][64];
    __shared__ float Ba[8][64];
    __shared__ float Wss[8][128];
    __shared__ float Wns[8][128];

    int m0 = blockIdx.x * 64;
    int tid = threadIdx.x;
    int tx = tid & 15;   // column group: cols tx*8 .. tx*8+7
    int ty = tid >> 4;   // row group:    rows ty*4 .. ty*4+3

    unsigned long long acc[4][4];
#pragma unroll
    for (int r = 0; r < 4; r++)
#pragma unroll
        for (int cp = 0; cp < 4; cp++) acc[r][cp] = 0ull;

    for (int kt = 0; kt < 16; kt++) {
        int kk = kt * 8;
#pragma unroll
        for (int i = 0; i < 2; i++) {
            int idx = tid + i * 256;
            int m = idx >> 3, k = idx & 7;
            int row = m0 + m;
            float a = 0.f, b = 0.f;
            if (row < N_NODES) {
                a = g_h1[row * 128 + kk + k];
                b = g_agg1[row * 128 + kk + k] * g_invdeg[row];
            }
            As[k][m] = a;
            Ba[k][m] = b;
        }
#pragma unroll
        for (int i = 0; i < 4; i++) {
            int idx = tid + i * 256;
            int k = idx >> 7, n = idx & 127;
            Wss[k][n] = Ws[(kk + k) * 128 + n];
            Wns[k][n] = Wn[(kk + k) * 128 + n];
        }
        __syncthreads();
#pragma unroll
        for (int k = 0; k < 8; k++) {
            float4 a4 = *reinterpret_cast<const float4*>(&As[k][ty * 4]);
            float4 b4 = *reinterpret_cast<const float4*>(&Ba[k][ty * 4]);
            unsigned long long ad[4] = {dup2(a4.x), dup2(a4.y), dup2(a4.z), dup2(a4.w)};
            unsigned long long bd[4] = {dup2(b4.x), dup2(b4.y), dup2(b4.z), dup2(b4.w)};
            const unsigned long long* wsp =
                reinterpret_cast<const unsigned long long*>(&Wss[k][tx * 8]);
            const unsigned long long* wnp =
                reinterpret_cast<const unsigned long long*>(&Wns[k][tx * 8]);
#pragma unroll
            for (int cp = 0; cp < 4; cp++) {
                unsigned long long w2s = wsp[cp];
                unsigned long long w2n = wnp[cp];
#pragma unroll
                for (int r = 0; r < 4; r++) {
                    fma2(acc[r][cp], ad[r], w2s);
                    fma2(acc[r][cp], bd[r], w2n);
                }
            }
        }
        __syncthreads();
    }

    int colbase = tx * 8;
    float bias[8];
#pragma unroll
    for (int c = 0; c < 8; c++) bias[c] = bs[colbase + c] + bn[colbase + c];

#pragma unroll
    for (int r = 0; r < 4; r++) {
        int row = m0 + ty * 4 + r;
        if (row >= N_NODES) continue;
        float v[8];
#pragma unroll
        for (int cp = 0; cp < 4; cp++) unpack2(acc[r][cp], v[2 * cp], v[2 * cp + 1]);
#pragma unroll
        for (int c = 0; c < 8; c++) v[c] = fmaxf(v[c] + bias[c], 0.f);
        int g = __ldg(&batch[row]);
        const float* p = g_pooled + g * HID + colbase;
        red4(p, make_float4(v[0], v[1], v[2], v[3]));
        red4(p + 4, make_float4(v[4], v[5], v[6], v[7]));
    }
}

// ---------------- K11: heads ------------------------------------------------------
__global__ void k_heads(const float* __restrict__ Wr, const float* __restrict__ br,
                        const float* __restrict__ Wc, const float* __restrict__ bc,
                        float* __restrict__ out) {
    int g = blockIdx.x;
    int lane = threadIdx.x;
    float inv = 1.0f / fmaxf(g_cnt[g], 1.0f);
    float4 gv = *reinterpret_cast<const float4*>(g_pooled + g * HID + lane * 4);
    float gvals[4] = {gv.x * inv, gv.y * inv, gv.z * inv, gv.w * inv};

    float pr = 0.f;
#pragma unroll
    for (int i = 0; i < 4; i++) pr += gvals[i] * Wr[lane * 4 + i];
#pragma unroll
    for (int off = 16; off > 0; off >>= 1) pr += __shfl_xor_sync(0xffffffffu, pr, off);
    if (lane == 0) out[g] = pr + br[0];

    for (int o = 0; o < NCAT; o++) {
        float p = 0.f;
#pragma unroll
        for (int i = 0; i < 4; i++) p += gvals[i] * Wc[(lane * 4 + i) * NCAT + o];
#pragma unroll
        for (int off = 16; off > 0; off >>= 1) p += __shfl_xor_sync(0xffffffffu, p, off);
        if (lane == 0) out[N_GRAPHS + g * NCAT + o] = p + bc[o];
    }
}

// ---------------- launch ----------------
extern "C" void kernel_launch(void* const* d_in, const int* in_sizes, int n_in,
                              void* d_out, int out_size) {
    const int*   node_type = (const int*)d_in[0];
    const int*   ident     = (const int*)d_in[1];
    const float* flags     = (const float*)d_in[2];
    const int*   depth     = (const int*)d_in[3];
    const int*   edge      = (const int*)d_in[4];
    const int*   batch     = (const int*)d_in[5];
    const float* emb_node  = (const float*)d_in[6];
    const float* emb_ident = (const float*)d_in[7];
    const float* Ws0 = (const float*)d_in[8];
    const float* bs0 = (const float*)d_in[9];
    const float* Wn0 = (const float*)d_in[10];
    const float* bn0 = (const float*)d_in[11];
    const float* Ws1 = (const float*)d_in[12];
    const float* bs1 = (const float*)d_in[13];
    const float* Wn1 = (const float*)d_in[14];
    const float* bn1 = (const float*)d_in[15];
    const float* Wr  = (const float*)d_in[16];
    const float* br  = (const float*)d_in[17];
    const float* Wc  = (const float*)d_in[18];
    const float* bc  = (const float*)d_in[19];
    float* out = (float*)d_out;

    k_zero<<<512, 256>>>();
    k_stats<<<2048, 256>>>(edge, depth, batch);
    k_scan<<<1, 1024>>>();
    k_sortedges<<<2048, 256>>>(edge);
    k_table_id<<<2048, 256>>>(emb_ident, Ws0, Wn0);
    k_table_node<<<33, 256>>>(emb_node, Ws0, Wn0);
    k_nodefeat<<<2048, 256>>>(node_type, ident, flags, depth, Ws0, Wn0);
    k_agg0<<<(N_NODES + 7) / 8, 256>>>(bs0, bn0);
    k_agg1<<<(N_NODES + 7) / 8, 256>>>();
    k_gemm1<<<(N_NODES + 63) / 64, 256>>>(Ws1, Wn1, bs1, bn1, batch);
    k_heads<<<N_GRAPHS, 32>>>(Wr, br, Wc, bc, out);
}

// round 8
// speedup vs baseline: 2.2166x; 1.6683x over previous
#include <cuda_runtime.h>
#include <cuda_fp16.h>
#include <cstdint>

#define N_NODES 100000
#define N_EDGES 1600000
#define N_GRAPHS 512
#define HID 128
#define NCAT 10
#define NT_ROWS 258      // NODE_TYPE_BUCKETS + 2
#define ID_ROWS 50002    // IDENT_BUCKETS + 2

// ---------------- scratch (device globals; no runtime allocation) ----------------
__device__ __align__(16) float g_TNs[NT_ROWS * HID];
__device__ __align__(16) float g_TNn[NT_ROWS * HID];
__device__ __align__(16) float g_TIs[ID_ROWS * HID];
__device__ __align__(16) float g_TIn[ID_ROWS * HID];
__device__ __align__(16) float  g_self0[N_NODES * HID]; // x0 @ Ws0 (no bias)
__device__ __align__(16) __half g_y0h[N_NODES * HID];   // x0 @ Wn0 (fp16 gather operand)
// combined GEMM A operand: row = node, cols 0-127 = h1 (fp16), cols 128-255 = invdeg*agg(h1)
__device__ __align__(16) __half g_a1h[N_NODES * 256];
__device__ __align__(16) __half g_w1h[256 * 128];       // [Ws1; Wn1] fp16
__device__ int   g_deg[N_NODES];
__device__ int   g_off[N_NODES];
__device__ int   g_cursor[N_NODES];
__device__ int   g_bsum[512];
__device__ int   g_ssrc[N_EDGES];                       // src ids sorted by dst
__device__ float g_invdeg[N_NODES];
__device__ int   g_depthmax;
__device__ __align__(16) float g_pooled[N_GRAPHS * HID];
__device__ float g_cnt[N_GRAPHS];

// ---------------- helpers --------------------------------------------------------
__device__ __forceinline__ unsigned long long dup2(float a) {
    unsigned long long r;
    asm("mov.b64 %0, {%1, %1};" : "=l"(r) : "f"(a));
    return r;
}
__device__ __forceinline__ void fma2(unsigned long long& acc, unsigned long long a,
                                     unsigned long long b) {
    asm("fma.rn.f32x2 %0, %1, %2, %0;" : "+l"(acc) : "l"(a), "l"(b));
}
__device__ __forceinline__ void unpack2(unsigned long long v, float& lo, float& hi) {
    asm("mov.b64 {%0, %1}, %2;" : "=f"(lo), "=f"(hi) : "l"(v));
}
__device__ __forceinline__ float4 ld4(const float* p) {
    return *reinterpret_cast<const float4*>(p);
}
__device__ __forceinline__ void add4(float4& a, float4 b) {
    a.x += b.x; a.y += b.y; a.z += b.z; a.w += b.w;
}
__device__ __forceinline__ void fma4(float4& a, float s, float4 b) {
    a.x += s * b.x; a.y += s * b.y; a.z += s * b.z; a.w += s * b.w;
}
__device__ __forceinline__ void red2(const float* p, float x, float y) {
    asm volatile("red.global.add.v2.f32 [%0], {%1,%2};"
                 :: "l"(p), "f"(x), "f"(y) : "memory");
}
__device__ __forceinline__ void haccu(float4& a, uint2 u) {
    __half2 h0 = *reinterpret_cast<const __half2*>(&u.x);
    __half2 h1 = *reinterpret_cast<const __half2*>(&u.y);
    float2 f0 = __half22float2(h0);
    float2 f1 = __half22float2(h1);
    a.x += f0.x; a.y += f0.y; a.z += f1.x; a.w += f1.y;
}
__device__ __forceinline__ void st4h(__half* p, float4 v) {
    __half2 h0 = __floats2half2_rn(v.x, v.y);
    __half2 h1 = __floats2half2_rn(v.z, v.w);
    uint2 u;
    u.x = *reinterpret_cast<const uint32_t*>(&h0);
    u.y = *reinterpret_cast<const uint32_t*>(&h1);
    *reinterpret_cast<uint2*>(p) = u;
}
__device__ __forceinline__ uint32_t smem_u32(const void* p) {
    uint32_t a;
    asm("{ .reg .u64 t; cvta.to.shared.u64 t, %1; cvt.u32.u64 %0, t; }" : "=r"(a) : "l"(p));
    return a;
}
#define LDSM4(r0, r1, r2, r3, addr)                                             \
    asm volatile("ldmatrix.sync.aligned.m8n8.x4.shared.b16 {%0,%1,%2,%3}, [%4];" \
                 : "=r"(r0), "=r"(r1), "=r"(r2), "=r"(r3) : "r"(addr))
#define LDSM4T(r0, r1, r2, r3, addr)                                                  \
    asm volatile("ldmatrix.sync.aligned.m8n8.x4.trans.shared.b16 {%0,%1,%2,%3}, [%4];" \
                 : "=r"(r0), "=r"(r1), "=r"(r2), "=r"(r3) : "r"(addr))
#define MMA16816(d, a, b0, b1)                                                     \
    asm volatile(                                                                  \
        "mma.sync.aligned.m16n8k16.row.col.f32.f16.f16.f32 "                       \
        "{%0,%1,%2,%3}, {%4,%5,%6,%7}, {%8,%9}, {%0,%1,%2,%3};"                    \
        : "+f"((d)[0]), "+f"((d)[1]), "+f"((d)[2]), "+f"((d)[3])                   \
        : "r"((a)[0]), "r"((a)[1]), "r"((a)[2]), "r"((a)[3]), "r"(b0), "r"(b1))

// ---------------- K1: zero small state -------------------------------------------
__global__ void k_zero() {
    int tid = blockIdx.x * blockDim.x + threadIdx.x;
    int stride = gridDim.x * blockDim.x;
    for (int i = tid; i < N_NODES; i += stride) { g_deg[i] = 0; g_cursor[i] = 0; }
    for (int i = tid; i < N_GRAPHS * HID; i += stride) g_pooled[i] = 0.f;
    for (int i = tid; i < N_GRAPHS; i += stride) g_cnt[i] = 0.f;
    if (tid == 0) g_depthmax = 0;
}

// ---------------- K2: degrees, depth max, graph counts ----------------------------
__global__ void k_stats(const int* __restrict__ edge, const int* __restrict__ depth,
                        const int* __restrict__ batch) {
    int tid = blockIdx.x * blockDim.x + threadIdx.x;
    int stride = gridDim.x * blockDim.x;
    for (int e = tid; e < N_EDGES; e += stride)
        atomicAdd(&g_deg[edge[N_EDGES + e]], 1);
    int dm = 0;
    for (int i = tid; i < N_NODES; i += stride) dm = max(dm, depth[i]);
    dm = __reduce_max_sync(0xffffffffu, dm);
    if ((threadIdx.x & 31) == 0) atomicMax(&g_depthmax, dm);
    for (int i = tid; i < N_NODES; i += stride)
        atomicAdd(&g_cnt[batch[i]], 1.0f);
}

// ---------------- K3a/b/c: multi-block exclusive scan of degrees ------------------
__global__ void k_scan1() {   // one block per 256 elements
    __shared__ int ws[8];
    int b = blockIdx.x, tid = threadIdx.x;
    int lane = tid & 31, wid = tid >> 5;
    int i = b * 256 + tid;
    int v = (i < N_NODES) ? g_deg[i] : 0;
    int x = v;
#pragma unroll
    for (int o = 1; o < 32; o <<= 1) {
        int y = __shfl_up_sync(0xffffffffu, x, o);
        if (lane >= o) x += y;
    }
    if (lane == 31) ws[wid] = x;
    __syncthreads();
    if (tid < 8) {
        int s = ws[tid];
#pragma unroll
        for (int o = 1; o < 8; o <<= 1) {
            int y = __shfl_up_sync(0xffu, s, o);
            if ((tid & 7) >= o) s += y;
        }
        ws[tid] = s;
    }
    __syncthreads();
    int pre = (wid > 0) ? ws[wid - 1] : 0;
    if (i < N_NODES) g_off[i] = pre + x - v;
    if (tid == 255) g_bsum[b] = pre + x;
}
__global__ void k_scan2() {   // 1 block x 512: exclusive scan of block sums
    __shared__ int ws[16];
    int tid = threadIdx.x;
    int lane = tid & 31, wid = tid >> 5;
    int v = (tid < 512) ? g_bsum[tid] : 0;
    int x = v;
#pragma unroll
    for (int o = 1; o < 32; o <<= 1) {
        int y = __shfl_up_sync(0xffffffffu, x, o);
        if (lane >= o) x += y;
    }
    if (lane == 31) ws[wid] = x;
    __syncthreads();
    if (tid < 16) {
        int s = ws[tid];
#pragma unroll
        for (int o = 1; o < 16; o <<= 1) {
            int y = __shfl_up_sync(0xffffu, s, o);
            if ((tid & 15) >= o) s += y;
        }
        ws[tid] = s;
    }
    __syncthreads();
    int pre = (wid > 0) ? ws[wid - 1] : 0;
    g_bsum[tid] = pre + x - v;
}
__global__ void k_scan3() {
    int i = blockIdx.x * blockDim.x + threadIdx.x;
    if (i < N_NODES) g_off[i] += g_bsum[i >> 8];
}

// ---------------- K4: bucket edges by destination ---------------------------------
__global__ void k_sortedges(const int* __restrict__ edge) {
    int tid = blockIdx.x * blockDim.x + threadIdx.x;
    int stride = gridDim.x * blockDim.x;
    for (int e = tid; e < N_EDGES; e += stride) {
        int s = edge[e];
        int d = edge[N_EDGES + e];
        int p = atomicAdd(&g_cursor[d], 1);
        g_ssrc[g_off[d] + p] = s;
    }
}

// ---------------- K5: ident embedding tables --------------------------------------
__global__ __launch_bounds__(256) void k_table_id(const float* __restrict__ embi,
                                                  const float* __restrict__ Ws0,
                                                  const float* __restrict__ Wn0) {
    __shared__ float sW[32][128];
    __shared__ float nW[32][128];
    int tid = threadIdx.x;
    for (int i = tid; i < 32 * 128; i += 256) {
        int k = i >> 7, n = i & 127;
        sW[k][n] = Ws0[(64 + k) * 128 + n];
        nW[k][n] = Wn0[(64 + k) * 128 + n];
    }
    __syncthreads();
    int lane = tid & 31;
    int gw = (blockIdx.x * 256 + tid) >> 5;
    int nwarps = (gridDim.x * 256) >> 5;
    for (int r = gw; r < ID_ROWS; r += nwarps) {
        float me = embi[r * 32 + lane];
        unsigned long long as0 = 0, as1 = 0, an0 = 0, an1 = 0;
#pragma unroll
        for (int k = 0; k < 32; k++) {
            float e = __shfl_sync(0xffffffffu, me, k);
            unsigned long long e2 = dup2(e);
            const unsigned long long* ps =
                reinterpret_cast<const unsigned long long*>(&sW[k][lane * 4]);
            const unsigned long long* pn =
                reinterpret_cast<const unsigned long long*>(&nW[k][lane * 4]);
            fma2(as0, e2, ps[0]); fma2(as1, e2, ps[1]);
            fma2(an0, e2, pn[0]); fma2(an1, e2, pn[1]);
        }
        float v0, v1, v2, v3;
        unpack2(as0, v0, v1); unpack2(as1, v2, v3);
        *reinterpret_cast<float4*>(g_TIs + r * 128 + lane * 4) = make_float4(v0, v1, v2, v3);
        unpack2(an0, v0, v1); unpack2(an1, v2, v3);
        *reinterpret_cast<float4*>(g_TIn + r * 128 + lane * 4) = make_float4(v0, v1, v2, v3);
    }
}

// ---------------- K6: node-type embedding tables ----------------------------------
__global__ void k_table_node(const float* __restrict__ embn,
                             const float* __restrict__ Ws0,
                             const float* __restrict__ Wn0) {
    int tid = threadIdx.x;
    int lane = tid & 31;
    int gw = (blockIdx.x * 256 + tid) >> 5;
    int nwarps = (gridDim.x * 256) >> 5;
    for (int r = gw; r < NT_ROWS; r += nwarps) {
        float me0 = embn[r * 64 + lane];
        float me1 = embn[r * 64 + 32 + lane];
        float4 as = make_float4(0, 0, 0, 0), an = make_float4(0, 0, 0, 0);
#pragma unroll
        for (int k = 0; k < 64; k++) {
            float e = (k < 32) ? __shfl_sync(0xffffffffu, me0, k)
                               : __shfl_sync(0xffffffffu, me1, k - 32);
            float4 ws = ld4(Ws0 + k * 128 + lane * 4);
            float4 wn = ld4(Wn0 + k * 128 + lane * 4);
            fma4(as, e, ws);
            fma4(an, e, wn);
        }
        *reinterpret_cast<float4*>(g_TNs + r * 128 + lane * 4) = as;
        *reinterpret_cast<float4*>(g_TNn + r * 128 + lane * 4) = an;
    }
}

// ---------------- K6b: weights [Ws1; Wn1] -> fp16 ---------------------------------
__global__ void k_wh(const float* __restrict__ Ws, const float* __restrict__ Wn) {
    int i = blockIdx.x * blockDim.x + threadIdx.x;
    if (i < 256 * 128) {
        int r = i >> 7, n = i & 127;
        float v = (r < 128) ? Ws[r * 128 + n] : Wn[(r - 128) * 128 + n];
        g_w1h[i] = __float2half(v);
    }
}

// ---------------- K7: per-node transformed features -------------------------------
__global__ void k_nodefeat(const int* __restrict__ nt, const int* __restrict__ ih,
                           const float* __restrict__ flags, const int* __restrict__ depth,
                           const float* __restrict__ Ws0, const float* __restrict__ Wn0) {
    int tid = threadIdx.x;
    int lane = tid & 31;
    int gw = (blockIdx.x * 256 + tid) >> 5;
    int nwarps = (gridDim.x * 256) >> 5;
    float inv_dmax = 1.0f / fmaxf((float)g_depthmax, 1.0f);
    int c4 = lane * 4;
    for (int i = gw; i < N_NODES; i += nwarps) {
        int t = nt[i], id = ih[i];
        float4 s = ld4(g_TNs + t * 128 + c4);
        add4(s, ld4(g_TIs + id * 128 + c4));
        float4 y = ld4(g_TNn + t * 128 + c4);
        add4(y, ld4(g_TIn + id * 128 + c4));
        float dn = (float)depth[i] * inv_dmax;
#pragma unroll
        for (int j = 0; j < 5; j++) {
            float f = __ldg(&flags[i * 5 + j]);
            fma4(s, f, ld4(Ws0 + (96 + j) * 128 + c4));
            fma4(y, f, ld4(Wn0 + (96 + j) * 128 + c4));
        }
        fma4(s, dn, ld4(Ws0 + 101 * 128 + c4));
        fma4(y, dn, ld4(Wn0 + 101 * 128 + c4));
        *reinterpret_cast<float4*>(g_self0 + i * 128 + c4) = s;
        st4h(g_y0h + i * 128 + c4, y);
        if (lane == 0) g_invdeg[i] = 1.0f / fmaxf((float)g_deg[i], 1.0f);
    }
}

// ---------------- K8: layer-0 aggregation (MLP=8) + epilogue ----------------------
// h1 = relu(self0 + invdeg*sum(y0h[src]) + bs0+bn0) -> g_a1h cols 0-127 (fp16)
__global__ __launch_bounds__(256) void k_agg0(const float* __restrict__ b1,
                                              const float* __restrict__ b2) {
    int tid = threadIdx.x;
    int lane = tid & 31;
    int d = blockIdx.x * 8 + (tid >> 5);
    if (d >= N_NODES) return;
    int c4 = lane * 4;
    int beg = g_off[d];
    int end = beg + g_deg[d];
    float4 a0 = make_float4(0, 0, 0, 0), a1 = a0, a2 = a0, a3 = a0;
    int k = beg;
    for (; k + 8 <= end; k += 8) {
        int s[8];
#pragma unroll
        for (int j = 0; j < 8; j++) s[j] = __ldg(&g_ssrc[k + j]);
        uint2 u[8];
#pragma unroll
        for (int j = 0; j < 8; j++)
            u[j] = *reinterpret_cast<const uint2*>(g_y0h + s[j] * 128 + c4);
        haccu(a0, u[0]); haccu(a1, u[1]); haccu(a2, u[2]); haccu(a3, u[3]);
        haccu(a0, u[4]); haccu(a1, u[5]); haccu(a2, u[6]); haccu(a3, u[7]);
    }
    for (; k < end; k++) {
        int s = __ldg(&g_ssrc[k]);
        haccu(a0, *reinterpret_cast<const uint2*>(g_y0h + s * 128 + c4));
    }
    add4(a0, a1); add4(a2, a3); add4(a0, a2);
    float inv = g_invdeg[d];
    float4 v = ld4(g_self0 + d * 128 + c4);
    fma4(v, inv, a0);
    float4 bias1 = __ldg(reinterpret_cast<const float4*>(b1 + c4));
    float4 bias2 = __ldg(reinterpret_cast<const float4*>(b2 + c4));
    v.x = fmaxf(v.x + bias1.x + bias2.x, 0.f);
    v.y = fmaxf(v.y + bias1.y + bias2.y, 0.f);
    v.z = fmaxf(v.z + bias1.z + bias2.z, 0.f);
    v.w = fmaxf(v.w + bias1.w + bias2.w, 0.f);
    st4h(g_a1h + d * 256 + c4, v);
}

// ---------------- K9: layer-1 aggregation (MLP=8) ---------------------------------
// g_a1h cols 128-255 = invdeg * sum(h1h[src])  (h1h = g_a1h cols 0-127)
__global__ __launch_bounds__(256) void k_agg1() {
    int tid = threadIdx.x;
    int lane = tid & 31;
    int d = blockIdx.x * 8 + (tid >> 5);
    if (d >= N_NODES) return;
    int c4 = lane * 4;
    int beg = g_off[d];
    int end = beg + g_deg[d];
    float4 a0 = make_float4(0, 0, 0, 0), a1 = a0, a2 = a0, a3 = a0;
    int k = beg;
    for (; k + 8 <= end; k += 8) {
        int s[8];
#pragma unroll
        for (int j = 0; j < 8; j++) s[j] = __ldg(&g_ssrc[k + j]);
        uint2 u[8];
#pragma unroll
        for (int j = 0; j < 8; j++)
            u[j] = *reinterpret_cast<const uint2*>(g_a1h + s[j] * 256 + c4);
        haccu(a0, u[0]); haccu(a1, u[1]); haccu(a2, u[2]); haccu(a3, u[3]);
        haccu(a0, u[4]); haccu(a1, u[5]); haccu(a2, u[6]); haccu(a3, u[7]);
    }
    for (; k < end; k++) {
        int s = __ldg(&g_ssrc[k]);
        haccu(a0, *reinterpret_cast<const uint2*>(g_a1h + s * 256 + c4));
    }
    add4(a0, a1); add4(a2, a3); add4(a0, a2);
    float inv = g_invdeg[d];
    a0.x *= inv; a0.y *= inv; a0.z *= inv; a0.w *= inv;
    st4h(g_a1h + d * 256 + 128 + c4, a0);
}

// ---------------- K10: tensor-core GEMM + bias + relu + pool ----------------------
// out[128-tile x 128] = relu(g_a1h[Mx256] @ g_w1h[256x128] + bs1 + bn1); red -> pooled
__global__ __launch_bounds__(256) void k_gemm_h(const float* __restrict__ bs,
                                                const float* __restrict__ bn,
                                                const int* __restrict__ batch) {
    __shared__ __half As[128][48];   // 32 K-halves per row + 16 pad (96B row: 16B-aligned)
    __shared__ __half Bs[32][136];   // 128 N-halves per row + 8 pad (272B row: 16B-aligned)
    int tid = threadIdx.x;
    int lane = tid & 31, wid = tid >> 5;
    int wm = wid & 3;                 // rows wm*32..+31
    int wn = wid >> 2;                // cols wn*64..+63
    int m0 = blockIdx.x * 128;

    float acc[2][8][4];
#pragma unroll
    for (int mi = 0; mi < 2; mi++)
#pragma unroll
        for (int ni = 0; ni < 8; ni++)
#pragma unroll
            for (int q = 0; q < 4; q++) acc[mi][ni][q] = 0.f;

    uint32_t sA = smem_u32(As), sB = smem_u32(Bs);

    for (int kt = 0; kt < 8; kt++) {
        int kk = kt * 32;
        // load A tile: 128 rows x 32 halves (512 chunks of 8 halves, 4 chunks/row)
#pragma unroll
        for (int i = 0; i < 2; i++) {
            int idx = tid + i * 256;
            int row = idx >> 2, seg = idx & 3;
            uint4 v = make_uint4(0, 0, 0, 0);
            int grow = m0 + row;
            if (grow < N_NODES)
                v = *reinterpret_cast<const uint4*>(g_a1h + grow * 256 + kk + seg * 8);
            *reinterpret_cast<uint4*>(&As[row][seg * 8]) = v;
        }
        // load B tile: 32 rows x 128 halves (512 chunks of 8 halves, 16 chunks/row)
#pragma unroll
        for (int i = 0; i < 2; i++) {
            int idx = tid + i * 256;
            int row = idx >> 4, seg = idx & 15;
            uint4 v = *reinterpret_cast<const uint4*>(g_w1h + (kk + row) * 128 + seg * 8);
            *reinterpret_cast<uint4*>(&Bs[row][seg * 8]) = v;
        }
        __syncthreads();
#pragma unroll
        for (int ks = 0; ks < 32; ks += 16) {
            uint32_t afr[2][4];
#pragma unroll
            for (int mi = 0; mi < 2; mi++) {
                uint32_t addr = sA + ((wm * 32 + mi * 16 + (lane & 15)) * 48 +
                                      ks + ((lane >> 4) << 3)) * 2;
                LDSM4(afr[mi][0], afr[mi][1], afr[mi][2], afr[mi][3], addr);
            }
            uint32_t bfr[8][2];
#pragma unroll
            for (int nq = 0; nq < 4; nq++) {
                uint32_t addr = sB + ((ks + (lane & 7) + ((lane >> 3) & 1) * 8) * 136 +
                                      wn * 64 + nq * 16 + ((lane >> 4) & 1) * 8) * 2;
                LDSM4T(bfr[nq * 2][0], bfr[nq * 2][1], bfr[nq * 2 + 1][0],
                       bfr[nq * 2 + 1][1], addr);
            }
#pragma unroll
            for (int mi = 0; mi < 2; mi++)
#pragma unroll
                for (int ni = 0; ni < 8; ni++)
                    MMA16816(acc[mi][ni], afr[mi], bfr[ni][0], bfr[ni][1]);
        }
        __syncthreads();
    }

    // epilogue: bias + relu + red into pooled
    int tg = lane & 3, rg = lane >> 2;
#pragma unroll
    for (int mi = 0; mi < 2; mi++) {
        int r0 = m0 + wm * 32 + mi * 16 + rg;
        int r1 = r0 + 8;
        int bi0 = (r0 < N_NODES) ? __ldg(&batch[r0]) : -1;
        int bi1 = (r1 < N_NODES) ? __ldg(&batch[r1]) : -1;
#pragma unroll
        for (int ni = 0; ni < 8; ni++) {
            int c = wn * 64 + ni * 8 + tg * 2;
            float bb0 = __ldg(&bs[c]) + __ldg(&bn[c]);
            float bb1 = __ldg(&bs[c + 1]) + __ldg(&bn[c + 1]);
            float* ac = acc[mi][ni];
            if (bi0 >= 0)
                red2(g_pooled + bi0 * 128 + c,
                     fmaxf(ac[0] + bb0, 0.f), fmaxf(ac[1] + bb1, 0.f));
            if (bi1 >= 0)
                red2(g_pooled + bi1 * 128 + c,
                     fmaxf(ac[2] + bb0, 0.f), fmaxf(ac[3] + bb1, 0.f));
        }
    }
}

// ---------------- K11: heads ------------------------------------------------------
__global__ void k_heads(const float* __restrict__ Wr, const float* __restrict__ br,
                        const float* __restrict__ Wc, const float* __restrict__ bc,
                        float* __restrict__ out) {
    int g = blockIdx.x;
    int lane = threadIdx.x;
    float inv = 1.0f / fmaxf(g_cnt[g], 1.0f);
    float4 gv = *reinterpret_cast<const float4*>(g_pooled + g * HID + lane * 4);
    float gvals[4] = {gv.x * inv, gv.y * inv, gv.z * inv, gv.w * inv};

    float pr = 0.f;
#pragma unroll
    for (int i = 0; i < 4; i++) pr += gvals[i] * Wr[lane * 4 + i];
#pragma unroll
    for (int off = 16; off > 0; off >>= 1) pr += __shfl_xor_sync(0xffffffffu, pr, off);
    if (lane == 0) out[g] = pr + br[0];

    for (int o = 0; o < NCAT; o++) {
        float p = 0.f;
#pragma unroll
        for (int i = 0; i < 4; i++) p += gvals[i] * Wc[(lane * 4 + i) * NCAT + o];
#pragma unroll
        for (int off = 16; off > 0; off >>= 1) p += __shfl_xor_sync(0xffffffffu, p, off);
        if (lane == 0) out[N_GRAPHS + g * NCAT + o] = p + bc[o];
    }
}

// ---------------- launch ----------------
extern "C" void kernel_launch(void* const* d_in, const int* in_sizes, int n_in,
                              void* d_out, int out_size) {
    const int*   node_type = (const int*)d_in[0];
    const int*   ident     = (const int*)d_in[1];
    const float* flags     = (const float*)d_in[2];
    const int*   depth     = (const int*)d_in[3];
    const int*   edge      = (const int*)d_in[4];
    const int*   batch     = (const int*)d_in[5];
    const float* emb_node  = (const float*)d_in[6];
    const float* emb_ident = (const float*)d_in[7];
    const float* Ws0 = (const float*)d_in[8];
    const float* bs0 = (const float*)d_in[9];
    const float* Wn0 = (const float*)d_in[10];
    const float* bn0 = (const float*)d_in[11];
    const float* Ws1 = (const float*)d_in[12];
    const float* bs1 = (const float*)d_in[13];
    const float* Wn1 = (const float*)d_in[14];
    const float* bn1 = (const float*)d_in[15];
    const float* Wr  = (const float*)d_in[16];
    const float* br  = (const float*)d_in[17];
    const float* Wc  = (const float*)d_in[18];
    const float* bc  = (const float*)d_in[19];
    float* out = (float*)d_out;

    k_zero<<<512, 256>>>();
    k_stats<<<2048, 256>>>(edge, depth, batch);
    k_scan1<<<(N_NODES + 255) / 256, 256>>>();
    k_scan2<<<1, 512>>>();
    k_scan3<<<(N_NODES + 255) / 256, 256>>>();
    k_sortedges<<<2048, 256>>>(edge);
    k_wh<<<128, 256>>>(Ws1, Wn1);
    k_table_id<<<2048, 256>>>(emb_ident, Ws0, Wn0);
    k_table_node<<<33, 256>>>(emb_node, Ws0, Wn0);
    k_nodefeat<<<2048, 256>>>(node_type, ident, flags, depth, Ws0, Wn0);
    k_agg0<<<(N_NODES + 7) / 8, 256>>>(bs0, bn0);
    k_agg1<<<(N_NODES + 7) / 8, 256>>>();
    k_gemm_h<<<(N_NODES + 127) / 128, 256>>>(bs1, bn1, batch);
    k_heads<<<N_GRAPHS, 32>>>(Wr, br, Wc, bc, out);
}